// round 1
// baseline (speedup 1.0000x reference)
#include <cuda_runtime.h>
#include <math.h>

#define B_ 8
#define N_ 4096
#define K_ 16
#define D_ 256
#define M_ (B_*N_)          // 32768 query rows

// Scratch (allocation-free rule: __device__ globals)
__device__ int   g_idx[M_*K_];        // 2 MB
__device__ float g_agg[M_*D_];        // 33.5 MB

// ---------------------------------------------------------------------------
// Kernel 1: brute-force kNN (top-16 smallest d2), matches jax top_k set
// d2 = |q|^2 + |m|^2 - 2 q.m  (same formula as reference)
// ---------------------------------------------------------------------------
__global__ __launch_bounds__(128) void knn_kernel(const float* __restrict__ coords)
{
    __shared__ float4 tile[128];
    int b = blockIdx.x >> 5;                       // 32 blocks per batch (4096/128)
    int q = ((blockIdx.x & 31) << 7) + threadIdx.x;
    const float* cb = coords + (size_t)b * N_ * 3;
    float qx = cb[q*3+0], qy = cb[q*3+1], qz = cb[q*3+2];
    float qsq = qx*qx + qy*qy + qz*qz;

    float best[K_];
    int   bidx[K_];
#pragma unroll
    for (int s = 0; s < K_; s++) { best[s] = 3.4e38f; bidx[s] = 0; }

    for (int m0 = 0; m0 < N_; m0 += 128) {
        __syncthreads();
        int m = m0 + threadIdx.x;
        float x = cb[m*3+0], y = cb[m*3+1], z = cb[m*3+2];
        tile[threadIdx.x] = make_float4(x, y, z, x*x + y*y + z*z);
        __syncthreads();
#pragma unroll 4
        for (int mm = 0; mm < 128; mm++) {
            float4 c = tile[mm];
            float d2 = qsq + c.w - 2.0f*(qx*c.x + qy*c.y + qz*c.z);
            if (d2 < best[K_-1]) {
                float d = d2; int id = m0 + mm;
                // sorted insert, strict < keeps earlier index on ties (jax tie-break)
#pragma unroll
                for (int s = 0; s < K_; s++) {
                    if (d < best[s]) {
                        float td = best[s]; int ti = bidx[s];
                        best[s] = d; bidx[s] = id;
                        d = td; id = ti;
                    }
                }
            }
        }
    }
    int* o = g_idx + (size_t)(b*N_ + q) * K_;
#pragma unroll
    for (int s = 0; s < K_; s++) o[s] = bidx[s];
}

// ---------------------------------------------------------------------------
// Warp-per-row LayerNorm over smem rows (256-thread blocks = 8 warps)
// ---------------------------------------------------------------------------
template<int W, bool RELU>
__device__ __forceinline__ void ln_rows(float* buf, int rows,
                                        const float* __restrict__ g,
                                        const float* __restrict__ be)
{
    const int wid = threadIdx.x >> 5, lane = threadIdx.x & 31;
    constexpr int C = W / 32;
    for (int r = wid; r < rows; r += 8) {
        float* h = buf + r * W;
        float v[C]; float s = 0.f;
#pragma unroll
        for (int i = 0; i < C; i++) { v[i] = h[lane + i*32]; s += v[i]; }
#pragma unroll
        for (int o = 16; o; o >>= 1) s += __shfl_xor_sync(0xffffffffu, s, o);
        float mean = s * (1.0f / W);
        float s2 = 0.f;
#pragma unroll
        for (int i = 0; i < C; i++) { float d = v[i] - mean; s2 += d*d; }
#pragma unroll
        for (int o = 16; o; o >>= 1) s2 += __shfl_xor_sync(0xffffffffu, s2, o);
        float rstd = rsqrtf(s2 * (1.0f / W) + 1e-5f);
#pragma unroll
        for (int i = 0; i < C; i++) {
            int c = lane + i*32;
            float o2 = (v[i] - mean) * rstd * g[c] + be[c];
            if (RELU) o2 = fmaxf(o2, 0.f);
            h[c] = o2;
        }
    }
}

// ---------------------------------------------------------------------------
// Kernel 2: fused geom features + encoder MLP (10->64->128->256, LN each) + mean over K
// One block = 4 queries = 64 neighbor rows. 256 threads.
// smem: [0,32768) W3 staged; [32768,40960) bufA (64x128); [40960,57344) bufB (64x256)
// ---------------------------------------------------------------------------
#define ENC_G 4
#define ENC_R 64
#define ENC_SMEM_FLOATS (32768 + 8192 + 16384)

__global__ __launch_bounds__(256) void encoder_kernel(
    const float* __restrict__ coords,
    const float* __restrict__ W1, const float* __restrict__ b1,
    const float* __restrict__ g1, const float* __restrict__ be1,
    const float* __restrict__ W2, const float* __restrict__ b2,
    const float* __restrict__ g2, const float* __restrict__ be2,
    const float* __restrict__ W3, const float* __restrict__ b3,
    const float* __restrict__ g3, const float* __restrict__ be3)
{
    extern __shared__ float sm[];
    float* sW3  = sm;                 // 128*256
    float* bufA = sm + 32768;         // 64*128 (geom first, then h2)
    float* bufB = sm + 40960;         // 64*256 (h1 first, then h3)
    const int t = threadIdx.x;
    const int q0 = blockIdx.x * ENC_G;

    // stage W3 into smem (consumed in stage 3, after two syncs)
    for (int i = t; i < 128*256; i += 256) sW3[i] = W3[i];

    // geometric features: one thread per neighbor row
    if (t < ENC_R) {
        int q  = q0 + (t >> 4);
        int kk = t & 15;
        int b  = q >> 12;
        int n  = q & (N_ - 1);
        const float* cb = coords + (size_t)b * N_ * 3;
        float qx = cb[n*3+0], qy = cb[n*3+1], qz = cb[n*3+2];
        int nb = g_idx[(size_t)q * K_ + kk];
        float rx = cb[nb*3+0] - qx, ry = cb[nb*3+1] - qy, rz = cb[nb*3+2] - qz;
        float dist = sqrtf(rx*rx + ry*ry + rz*rz);
        float inv  = 1.0f / (dist + 1e-6f);
        float nx = rx*inv, ny = ry*inv, nz = rz*inv;
        float* gm = bufA + t * 10;
        gm[0] = dist; gm[1] = rx; gm[2] = ry; gm[3] = rz;
        gm[4] = atan2f(ny, nx); gm[5] = atan2f(nz, nx); gm[6] = atan2f(nz, ny);
        gm[7] = nx; gm[8] = ny; gm[9] = nz;
    }
    __syncthreads();

    // stage 1: geom[64][10] @ W1[10][64] -> h1 in bufB (stride 64)
    {
        int j = t & 63, grp = t >> 6;          // 4 groups x 16 rows
        float acc[16];
        float bj = b1[j];
#pragma unroll
        for (int r = 0; r < 16; r++) acc[r] = bj;
#pragma unroll
        for (int k = 0; k < 10; k++) {
            float w = W1[k*64 + j];
#pragma unroll
            for (int r = 0; r < 16; r++)
                acc[r] = fmaf(w, bufA[(grp*16 + r)*10 + k], acc[r]);
        }
#pragma unroll
        for (int r = 0; r < 16; r++) bufB[(grp*16 + r)*64 + j] = acc[r];
    }
    __syncthreads();
    ln_rows<64, true>(bufB, ENC_R, g1, be1);
    __syncthreads();

    // stage 2: h1[64][64] @ W2[64][128] -> h2 in bufA (stride 128)
    {
        int j = t & 127, half = t >> 7;        // 2 halves x 32 rows
        float acc[32];
        float bj = b2[j];
#pragma unroll
        for (int r = 0; r < 32; r++) acc[r] = bj;
        for (int k = 0; k < 64; k++) {
            float w = W2[k*128 + j];
#pragma unroll
            for (int r = 0; r < 32; r++)
                acc[r] = fmaf(w, bufB[(half*32 + r)*64 + k], acc[r]);
        }
#pragma unroll
        for (int r = 0; r < 32; r++) bufA[(half*32 + r)*128 + j] = acc[r];
    }
    __syncthreads();
    ln_rows<128, true>(bufA, ENC_R, g2, be2);
    __syncthreads();

    // stage 3: h2[64][128] @ W3[128][256] -> h3 in bufB (stride 256), W3 from smem
    {
        int j = t;
        float bj = b3[j];
        for (int c = 0; c < 4; c++) {          // 4 chunks x 16 rows
            float acc[16];
#pragma unroll
            for (int r = 0; r < 16; r++) acc[r] = bj;
            for (int k = 0; k < 128; k++) {
                float w = sW3[k*256 + j];
#pragma unroll
                for (int r = 0; r < 16; r++)
                    acc[r] = fmaf(w, bufA[(c*16 + r)*128 + k], acc[r]);
            }
#pragma unroll
            for (int r = 0; r < 16; r++) bufB[(c*16 + r)*256 + j] = acc[r];
        }
    }
    __syncthreads();
    ln_rows<256, false>(bufB, ENC_R, g3, be3);
    __syncthreads();

    // mean over K=16 neighbor rows per query -> g_agg
    {
        int j = t;
#pragma unroll
        for (int gq = 0; gq < ENC_G; gq++) {
            float s = 0.f;
#pragma unroll
            for (int r = 0; r < 16; r++) s += bufB[(gq*16 + r)*256 + j];
            g_agg[(size_t)(q0 + gq)*256 + j] = s * (1.0f/16.0f);
        }
    }
}

// ---------------------------------------------------------------------------
// Kernel 3: aggregator: relu(LN(agg@Wa1+ba1)) @ Wa2 + ba2
// One block = 32 rows, 256 threads. Dynamic smem: 2 * 32*256 floats = 64 KB.
// ---------------------------------------------------------------------------
#define AGG_RB 32
#define AGG_SMEM_FLOATS (2 * AGG_RB * 256)

__global__ __launch_bounds__(256) void agg_kernel(
    const float* __restrict__ Wa1, const float* __restrict__ ba1,
    const float* __restrict__ ga1, const float* __restrict__ bea1,
    const float* __restrict__ Wa2, const float* __restrict__ ba2,
    float* __restrict__ out)
{
    extern __shared__ float sm[];
    float* sin_  = sm;                  // [32][256]
    float* smid  = sm + AGG_RB*256;     // [32][256]
    const int t = threadIdx.x;
    const size_t r0 = (size_t)blockIdx.x * AGG_RB;

    for (int i = t; i < AGG_RB*256; i += 256) sin_[i] = g_agg[r0*256 + i];
    __syncthreads();

    int j = t;
    {   // stage A: agg @ Wa1 + ba1
        float bj = ba1[j];
        for (int c = 0; c < 2; c++) {
            float acc[16];
#pragma unroll
            for (int r = 0; r < 16; r++) acc[r] = bj;
            for (int k = 0; k < 256; k++) {
                float w = Wa1[k*256 + j];
#pragma unroll
                for (int r = 0; r < 16; r++)
                    acc[r] = fmaf(w, sin_[(c*16 + r)*256 + k], acc[r]);
            }
#pragma unroll
            for (int r = 0; r < 16; r++) smid[(c*16 + r)*256 + j] = acc[r];
        }
    }
    __syncthreads();
    ln_rows<256, true>(smid, AGG_RB, ga1, bea1);
    __syncthreads();
    {   // stage B: @ Wa2 + ba2 -> out
        float bj = ba2[j];
        for (int c = 0; c < 2; c++) {
            float acc[16];
#pragma unroll
            for (int r = 0; r < 16; r++) acc[r] = bj;
            for (int k = 0; k < 256; k++) {
                float w = Wa2[k*256 + j];
#pragma unroll
                for (int r = 0; r < 16; r++)
                    acc[r] = fmaf(w, smid[(c*16 + r)*256 + k], acc[r]);
            }
#pragma unroll
            for (int r = 0; r < 16; r++)
                out[(r0 + c*16 + r)*256 + j] = acc[r];
        }
    }
}

// ---------------------------------------------------------------------------
extern "C" void kernel_launch(void* const* d_in, const int* in_sizes, int n_in,
                              void* d_out, int out_size)
{
    const float* coords = (const float*)d_in[0];
    const float* W1  = (const float*)d_in[1];
    const float* b1  = (const float*)d_in[2];
    const float* g1  = (const float*)d_in[3];
    const float* be1 = (const float*)d_in[4];
    const float* W2  = (const float*)d_in[5];
    const float* b2  = (const float*)d_in[6];
    const float* g2  = (const float*)d_in[7];
    const float* be2 = (const float*)d_in[8];
    const float* W3  = (const float*)d_in[9];
    const float* b3  = (const float*)d_in[10];
    const float* g3  = (const float*)d_in[11];
    const float* be3 = (const float*)d_in[12];
    const float* Wa1 = (const float*)d_in[13];
    const float* ba1 = (const float*)d_in[14];
    const float* ga1 = (const float*)d_in[15];
    const float* bea1= (const float*)d_in[16];
    const float* Wa2 = (const float*)d_in[17];
    const float* ba2 = (const float*)d_in[18];
    float* out = (float*)d_out;

    cudaFuncSetAttribute(encoder_kernel,
                         cudaFuncAttributeMaxDynamicSharedMemorySize,
                         ENC_SMEM_FLOATS * (int)sizeof(float));
    cudaFuncSetAttribute(agg_kernel,
                         cudaFuncAttributeMaxDynamicSharedMemorySize,
                         AGG_SMEM_FLOATS * (int)sizeof(float));

    knn_kernel<<<B_ * (N_ / 128), 128>>>(coords);

    encoder_kernel<<<M_ / ENC_G, 256, ENC_SMEM_FLOATS * sizeof(float)>>>(
        coords, W1, b1, g1, be1, W2, b2, g2, be2, W3, b3, g3, be3);

    agg_kernel<<<M_ / AGG_RB, 256, AGG_SMEM_FLOATS * sizeof(float)>>>(
        Wa1, ba1, ga1, bea1, Wa2, ba2, out);
}

// round 2
// speedup vs baseline: 1.5993x; 1.5993x over previous
#include <cuda_runtime.h>
#include <math.h>

#define B_ 8
#define N_ 4096
#define K_ 16
#define D_ 256
#define M_ (B_*N_)          // 32768 query rows

__device__ int   g_idx[M_*K_];        // 2 MB
__device__ float g_agg[M_*D_];        // 33.5 MB

// ---------------------------------------------------------------------------
// Kernel 1: brute-force kNN, split-scan: 2 threads per query (half candidates
// each), sorted top-16 per half, then 2-way merge. 256 threads = 128 queries.
// ---------------------------------------------------------------------------
__global__ __launch_bounds__(256) void knn_kernel(const float* __restrict__ coords)
{
    __shared__ float4 tile[256];
    __shared__ float  sd[256 * K_];
    __shared__ int    si[256 * K_];

    const int t = threadIdx.x;
    const int b  = blockIdx.x >> 5;                 // 32 blocks per batch
    const int q0 = (blockIdx.x & 31) << 7;          // 128 queries per block
    const int q  = q0 + (t & 127);
    const int half = t >> 7;                        // 0: cand [0,2048), 1: [2048,4096)
    const float* cb = coords + (size_t)b * N_ * 3;

    float qx = cb[q*3+0], qy = cb[q*3+1], qz = cb[q*3+2];
    float qsq = qx*qx + qy*qy + qz*qz;

    float best[K_]; int bidx[K_];
#pragma unroll
    for (int s = 0; s < K_; s++) { best[s] = 3.4e38f; bidx[s] = 0; }

    const int base = half * 2048;
    for (int c0 = 0; c0 < 2048; c0 += 128) {
        __syncthreads();
        // cooperative load: t<128 loads range0 chunk, t>=128 range1 chunk
        {
            int m = (t < 128) ? (c0 + t) : (2048 + c0 + (t - 128));
            float x = cb[m*3+0], y = cb[m*3+1], z = cb[m*3+2];
            tile[t] = make_float4(x, y, z, x*x + y*y + z*z);
        }
        __syncthreads();
        const float4* tl = tile + half * 128;
#pragma unroll 4
        for (int mm = 0; mm < 128; mm++) {
            float4 c = tl[mm];
            float d2 = qsq + c.w - 2.0f*(qx*c.x + qy*c.y + qz*c.z);
            if (d2 < best[K_-1]) {
                float d = d2; int id = base + c0 + mm;
#pragma unroll
                for (int s = 0; s < K_; s++) {
                    if (d < best[s]) {
                        float td = best[s]; int ti = bidx[s];
                        best[s] = d; bidx[s] = id;
                        d = td; id = ti;
                    }
                }
            }
        }
    }

    // dump per-half sorted lists
#pragma unroll
    for (int s = 0; s < K_; s++) { sd[t*K_ + s] = best[s]; si[t*K_ + s] = bidx[s]; }
    __syncthreads();

    // merge: thread t<128 merges lists t and t+128 (lexicographic (d2, idx))
    if (t < 128) {
        const float* da = sd + t*K_;        const int* xa = si + t*K_;
        const float* db = sd + (t+128)*K_;  const int* xb = si + (t+128)*K_;
        int ia = 0, ib = 0;
        int* o = g_idx + (size_t)(b*N_ + q0 + t) * K_;
#pragma unroll
        for (int s = 0; s < K_; s++) {
            float va = (ia < K_) ? da[ia] : 3.4e38f;
            float vb = (ib < K_) ? db[ib] : 3.4e38f;
            bool takeA = (va < vb) || (va == vb && ((ia < K_ ? xa[ia] : 0x7fffffff) <
                                                    (ib < K_ ? xb[ib] : 0x7fffffff)));
            if (takeA) { o[s] = xa[ia]; ia++; }
            else       { o[s] = xb[ib]; ib++; }
        }
    }
}

// ---------------------------------------------------------------------------
// Warp-per-row LayerNorm over smem rows. NW warps in the block.
// ---------------------------------------------------------------------------
template<int W, bool RELU, int NW>
__device__ __forceinline__ void ln_rows(float* buf, int rows,
                                        const float* __restrict__ g,
                                        const float* __restrict__ be)
{
    const int wid = threadIdx.x >> 5, lane = threadIdx.x & 31;
    constexpr int C = W / 32;
    for (int r = wid; r < rows; r += NW) {
        float* h = buf + r * W;
        float v[C]; float s = 0.f;
#pragma unroll
        for (int i = 0; i < C; i++) { v[i] = h[lane + i*32]; s += v[i]; }
#pragma unroll
        for (int o = 16; o; o >>= 1) s += __shfl_xor_sync(0xffffffffu, s, o);
        float mean = s * (1.0f / W);
        float s2 = 0.f;
#pragma unroll
        for (int i = 0; i < C; i++) { float d = v[i] - mean; s2 += d*d; }
#pragma unroll
        for (int o = 16; o; o >>= 1) s2 += __shfl_xor_sync(0xffffffffu, s2, o);
        float rstd = rsqrtf(s2 * (1.0f / W) + 1e-5f);
#pragma unroll
        for (int i = 0; i < C; i++) {
            int c = lane + i*32;
            float o2 = (v[i] - mean) * rstd * g[c] + be[c];
            if (RELU) o2 = fmaxf(o2, 0.f);
            h[c] = o2;
        }
    }
}

__device__ __forceinline__ void fma_j4(float* acc, float a, float4 w) {
    acc[0] = fmaf(a, w.x, acc[0]); acc[1] = fmaf(a, w.y, acc[1]);
    acc[2] = fmaf(a, w.z, acc[2]); acc[3] = fmaf(a, w.w, acc[3]);
}
__device__ __forceinline__ void fma_j2(float* acc, float a, float2 w) {
    acc[0] = fmaf(a, w.x, acc[0]); acc[1] = fmaf(a, w.y, acc[1]);
}

// ---------------------------------------------------------------------------
// Kernel 2: fused geom features + encoder MLP (10->64->128->256) + mean over K
// One block = 4 queries = 64 neighbor rows, 512 threads (16 warps).
// smem: sW3 128KB | bufA 32KB (geom / h2) | bufB 64KB (h1 / h3) = 224KB
// Register tiling: 8 rows x {1,2,4} cols per thread, k unrolled x4, float4.
// ---------------------------------------------------------------------------
#define ENC_G 4
#define ENC_R 64
#define ENC_SMEM_FLOATS (32768 + 8192 + 16384)

__global__ __launch_bounds__(512, 1) void encoder_kernel(
    const float* __restrict__ coords,
    const float* __restrict__ W1, const float* __restrict__ b1,
    const float* __restrict__ g1, const float* __restrict__ be1,
    const float* __restrict__ W2, const float* __restrict__ b2,
    const float* __restrict__ g2, const float* __restrict__ be2,
    const float* __restrict__ W3, const float* __restrict__ b3,
    const float* __restrict__ g3, const float* __restrict__ be3)
{
    extern __shared__ float sm[];
    float* sW3  = sm;                 // 128*256
    float* bufA = sm + 32768;         // 64x128 (geom first, then h2)
    float* bufB = sm + 40960;         // 64x256 (h1 first, then h3)
    const int t = threadIdx.x;
    const int q0 = blockIdx.x * ENC_G;

    // stage W3 (used in stage 3, after several syncs)
    {
        float4* dst = (float4*)sW3; const float4* src = (const float4*)W3;
        for (int i = t; i < 32768/4; i += 512) dst[i] = src[i];
    }

    // geometric features: one thread per neighbor row
    if (t < ENC_R) {
        int q  = q0 + (t >> 4);
        int kk = t & 15;
        int b  = q >> 12;
        int n  = q & (N_ - 1);
        const float* cb = coords + (size_t)b * N_ * 3;
        float qx = cb[n*3+0], qy = cb[n*3+1], qz = cb[n*3+2];
        int nb = g_idx[(size_t)q * K_ + kk];
        float rx = cb[nb*3+0] - qx, ry = cb[nb*3+1] - qy, rz = cb[nb*3+2] - qz;
        float dist = sqrtf(rx*rx + ry*ry + rz*rz);
        float inv  = 1.0f / (dist + 1e-6f);
        float nx = rx*inv, ny = ry*inv, nz = rz*inv;
        float* gm = bufA + t * 10;
        gm[0] = dist; gm[1] = rx; gm[2] = ry; gm[3] = rz;
        gm[4] = atan2f(ny, nx); gm[5] = atan2f(nz, nx); gm[6] = atan2f(nz, ny);
        gm[7] = nx; gm[8] = ny; gm[9] = nz;
    }
    __syncthreads();

    const int chunk = t >> 6;          // 8 row-chunks of 8 rows
    const int r0 = chunk * 8;

    // ---- stage 1: geom[64][10] @ W1[10][64] -> bufB (stride 64) ----
    {
        int j = t & 63;
        float acc[8];
        float bj = b1[j];
#pragma unroll
        for (int r = 0; r < 8; r++) acc[r] = bj;
#pragma unroll
        for (int k = 0; k < 10; k++) {
            float w = W1[k*64 + j];
#pragma unroll
            for (int r = 0; r < 8; r++)
                acc[r] = fmaf(w, bufA[(r0 + r)*10 + k], acc[r]);
        }
#pragma unroll
        for (int r = 0; r < 8; r++) bufB[(r0 + r)*64 + j] = acc[r];
    }
    __syncthreads();
    ln_rows<64, true, 16>(bufB, ENC_R, g1, be1);
    __syncthreads();

    // ---- stage 2: h1[64][64] @ W2[64][128] -> bufA (stride 128) ----
    {
        int j0 = (t & 63) * 2;
        float acc[8][2];
        float2 bj = *(const float2*)&b2[j0];
#pragma unroll
        for (int r = 0; r < 8; r++) { acc[r][0] = bj.x; acc[r][1] = bj.y; }
        for (int k0 = 0; k0 < 64; k0 += 4) {
            float2 w0 = *(const float2*)&W2[(k0+0)*128 + j0];
            float2 w1 = *(const float2*)&W2[(k0+1)*128 + j0];
            float2 w2 = *(const float2*)&W2[(k0+2)*128 + j0];
            float2 w3 = *(const float2*)&W2[(k0+3)*128 + j0];
#pragma unroll
            for (int r = 0; r < 8; r++) {
                float4 a = *(const float4*)&bufB[(r0 + r)*64 + k0];
                fma_j2(acc[r], a.x, w0);
                fma_j2(acc[r], a.y, w1);
                fma_j2(acc[r], a.z, w2);
                fma_j2(acc[r], a.w, w3);
            }
        }
#pragma unroll
        for (int r = 0; r < 8; r++)
            *(float2*)&bufA[(r0 + r)*128 + j0] = make_float2(acc[r][0], acc[r][1]);
    }
    __syncthreads();
    ln_rows<128, true, 16>(bufA, ENC_R, g2, be2);
    __syncthreads();

    // ---- stage 3: h2[64][128] @ W3[128][256] -> bufB (stride 256) ----
    {
        int j0 = (t & 63) * 4;
        float acc[8][4];
        float4 bj = *(const float4*)&b3[j0];
#pragma unroll
        for (int r = 0; r < 8; r++) {
            acc[r][0] = bj.x; acc[r][1] = bj.y; acc[r][2] = bj.z; acc[r][3] = bj.w;
        }
        for (int k0 = 0; k0 < 128; k0 += 4) {
            float4 w0 = *(const float4*)&sW3[(k0+0)*256 + j0];
            float4 w1 = *(const float4*)&sW3[(k0+1)*256 + j0];
            float4 w2 = *(const float4*)&sW3[(k0+2)*256 + j0];
            float4 w3 = *(const float4*)&sW3[(k0+3)*256 + j0];
#pragma unroll
            for (int r = 0; r < 8; r++) {
                float4 a = *(const float4*)&bufA[(r0 + r)*128 + k0];
                fma_j4(acc[r], a.x, w0);
                fma_j4(acc[r], a.y, w1);
                fma_j4(acc[r], a.z, w2);
                fma_j4(acc[r], a.w, w3);
            }
        }
#pragma unroll
        for (int r = 0; r < 8; r++)
            *(float4*)&bufB[(r0 + r)*256 + j0] =
                make_float4(acc[r][0], acc[r][1], acc[r][2], acc[r][3]);
    }
    __syncthreads();
    ln_rows<256, false, 16>(bufB, ENC_R, g3, be3);
    __syncthreads();

    // mean over K=16 neighbor rows per query
    for (int idx = t; idx < ENC_G * 256; idx += 512) {
        int gq = idx >> 8, j = idx & 255;
        float s = 0.f;
#pragma unroll
        for (int r = 0; r < 16; r++) s += bufB[(gq*16 + r)*256 + j];
        g_agg[(size_t)(q0 + gq)*256 + j] = s * (1.0f/16.0f);
    }
}

// ---------------------------------------------------------------------------
// Kernel 3: aggregator: relu(LN(agg@Wa1+ba1)) @ Wa2 + ba2
// One block = 64 rows, 512 threads. smem: 2 * 64*256 floats = 128 KB.
// Tiling: 8 rows x 4 cols per thread, weights streamed from L2 (coalesced).
// ---------------------------------------------------------------------------
#define AGG_RB 64
#define AGG_SMEM_FLOATS (2 * AGG_RB * 256)

__global__ __launch_bounds__(512, 1) void agg_kernel(
    const float* __restrict__ Wa1, const float* __restrict__ ba1,
    const float* __restrict__ ga1, const float* __restrict__ bea1,
    const float* __restrict__ Wa2, const float* __restrict__ ba2,
    float* __restrict__ out)
{
    extern __shared__ float sm[];
    float* sin_  = sm;                  // [64][256]
    float* smid  = sm + AGG_RB*256;     // [64][256]
    const int t = threadIdx.x;
    const size_t row0 = (size_t)blockIdx.x * AGG_RB;

    {
        float4* dst = (float4*)sin_;
        const float4* src = (const float4*)(g_agg + row0*256);
        for (int i = t; i < AGG_RB*256/4; i += 512) dst[i] = src[i];
    }
    __syncthreads();

    const int chunk = t >> 6;          // 8 chunks x 8 rows
    const int r0 = chunk * 8;
    const int j0 = (t & 63) * 4;

    {   // stage A: sin @ Wa1 + ba1 -> smid
        float acc[8][4];
        float4 bj = *(const float4*)&ba1[j0];
#pragma unroll
        for (int r = 0; r < 8; r++) {
            acc[r][0] = bj.x; acc[r][1] = bj.y; acc[r][2] = bj.z; acc[r][3] = bj.w;
        }
        for (int k0 = 0; k0 < 256; k0 += 4) {
            float4 w0 = *(const float4*)&Wa1[(size_t)(k0+0)*256 + j0];
            float4 w1 = *(const float4*)&Wa1[(size_t)(k0+1)*256 + j0];
            float4 w2 = *(const float4*)&Wa1[(size_t)(k0+2)*256 + j0];
            float4 w3 = *(const float4*)&Wa1[(size_t)(k0+3)*256 + j0];
#pragma unroll
            for (int r = 0; r < 8; r++) {
                float4 a = *(const float4*)&sin_[(r0 + r)*256 + k0];
                fma_j4(acc[r], a.x, w0);
                fma_j4(acc[r], a.y, w1);
                fma_j4(acc[r], a.z, w2);
                fma_j4(acc[r], a.w, w3);
            }
        }
#pragma unroll
        for (int r = 0; r < 8; r++)
            *(float4*)&smid[(r0 + r)*256 + j0] =
                make_float4(acc[r][0], acc[r][1], acc[r][2], acc[r][3]);
    }
    __syncthreads();
    ln_rows<256, true, 16>(smid, AGG_RB, ga1, bea1);
    __syncthreads();
    {   // stage B: smid @ Wa2 + ba2 -> out
        float acc[8][4];
        float4 bj = *(const float4*)&ba2[j0];
#pragma unroll
        for (int r = 0; r < 8; r++) {
            acc[r][0] = bj.x; acc[r][1] = bj.y; acc[r][2] = bj.z; acc[r][3] = bj.w;
        }
        for (int k0 = 0; k0 < 256; k0 += 4) {
            float4 w0 = *(const float4*)&Wa2[(size_t)(k0+0)*256 + j0];
            float4 w1 = *(const float4*)&Wa2[(size_t)(k0+1)*256 + j0];
            float4 w2 = *(const float4*)&Wa2[(size_t)(k0+2)*256 + j0];
            float4 w3 = *(const float4*)&Wa2[(size_t)(k0+3)*256 + j0];
#pragma unroll
            for (int r = 0; r < 8; r++) {
                float4 a = *(const float4*)&smid[(r0 + r)*256 + k0];
                fma_j4(acc[r], a.x, w0);
                fma_j4(acc[r], a.y, w1);
                fma_j4(acc[r], a.z, w2);
                fma_j4(acc[r], a.w, w3);
            }
        }
#pragma unroll
        for (int r = 0; r < 8; r++)
            *(float4*)&out[(row0 + r0 + r)*256 + j0] =
                make_float4(acc[r][0], acc[r][1], acc[r][2], acc[r][3]);
    }
}

// ---------------------------------------------------------------------------
extern "C" void kernel_launch(void* const* d_in, const int* in_sizes, int n_in,
                              void* d_out, int out_size)
{
    const float* coords = (const float*)d_in[0];
    const float* W1  = (const float*)d_in[1];
    const float* b1  = (const float*)d_in[2];
    const float* g1  = (const float*)d_in[3];
    const float* be1 = (const float*)d_in[4];
    const float* W2  = (const float*)d_in[5];
    const float* b2  = (const float*)d_in[6];
    const float* g2  = (const float*)d_in[7];
    const float* be2 = (const float*)d_in[8];
    const float* W3  = (const float*)d_in[9];
    const float* b3  = (const float*)d_in[10];
    const float* g3  = (const float*)d_in[11];
    const float* be3 = (const float*)d_in[12];
    const float* Wa1 = (const float*)d_in[13];
    const float* ba1 = (const float*)d_in[14];
    const float* ga1 = (const float*)d_in[15];
    const float* bea1= (const float*)d_in[16];
    const float* Wa2 = (const float*)d_in[17];
    const float* ba2 = (const float*)d_in[18];
    float* out = (float*)d_out;

    cudaFuncSetAttribute(encoder_kernel,
                         cudaFuncAttributeMaxDynamicSharedMemorySize,
                         ENC_SMEM_FLOATS * (int)sizeof(float));
    cudaFuncSetAttribute(agg_kernel,
                         cudaFuncAttributeMaxDynamicSharedMemorySize,
                         AGG_SMEM_FLOATS * (int)sizeof(float));

    knn_kernel<<<B_ * (N_ / 128), 256>>>(coords);

    encoder_kernel<<<M_ / ENC_G, 512, ENC_SMEM_FLOATS * sizeof(float)>>>(
        coords, W1, b1, g1, be1, W2, b2, g2, be2, W3, b3, g3, be3);

    agg_kernel<<<M_ / AGG_RB, 512, AGG_SMEM_FLOATS * sizeof(float)>>>(
        Wa1, ba1, ga1, bea1, Wa2, ba2, out);
}